// round 12
// baseline (speedup 1.0000x reference)
#include <cuda_runtime.h>
#include <cuda_bf16.h>
#include <cuda_fp16.h>
#include <cstdint>

#define N_NODES  100000
#define N_PAD    100096          // 782 * 128
#define N_EDGES  1600000
#define N_GRAPHS 100
#define SCAN_B   1024
#define NB_SCAN  98

// ---------------- scratch (static __device__ allocations only) ----------------
__device__ __half g_a [N_PAD * 128];          // activations, fp16, pitch 128
__device__ __half g_bh[3 * 256 * 128];        // B hi planes, layer l at offset l*32768
__device__ __half g_bl[3 * 256 * 128];        // B lo planes (fp16 residual)
__device__ __half g_yn[N_PAD * 128];          // neighbor-transform out (fp16)
__device__ float  g_ys[N_PAD * 128];          // self-transform out (fp32)
__device__ float  g_h3[N_NODES * 104];        // layer-3 activation (fp32, pitch 104)
__device__ float g_invdeg[N_NODES];
__device__ int   g_rowcnt[N_NODES];
__device__ int   g_rowptr[N_NODES];
__device__ int   g_cursor[N_NODES];
__device__ int   g_csr[N_EDGES];
__device__ int   g_bsum[128];
__device__ float g_pool[N_GRAPHS * 5];
__device__ int   g_gcnt[N_GRAPHS];

// ---------------- PTX helpers ----------------
__device__ __forceinline__ uint32_t smem_u32(const void* p) {
    uint32_t a;
    asm("{ .reg .u64 t; cvta.to.shared.u64 t, %1; cvt.u32.u64 %0, t; }" : "=r"(a) : "l"(p));
    return a;
}
__device__ __forceinline__ void ldsm4(uint32_t* r, uint32_t addr) {
    asm volatile("ldmatrix.sync.aligned.m8n8.x4.shared.b16 {%0,%1,%2,%3}, [%4];"
                 : "=r"(r[0]), "=r"(r[1]), "=r"(r[2]), "=r"(r[3]) : "r"(addr));
}
__device__ __forceinline__ void mma16816h(float* c, const uint32_t* a,
                                          uint32_t b0, uint32_t b1) {
    asm volatile(
        "mma.sync.aligned.m16n8k16.row.col.f32.f16.f16.f32 "
        "{%0,%1,%2,%3}, {%4,%5,%6,%7}, {%8,%9}, {%0,%1,%2,%3};"
        : "+f"(c[0]), "+f"(c[1]), "+f"(c[2]), "+f"(c[3])
        : "r"(a[0]), "r"(a[1]), "r"(a[2]), "r"(a[3]), "r"(b0), "r"(b1));
}
__device__ __forceinline__ void cpa16(uint32_t d, const void* g) {
    asm volatile("cp.async.cg.shared.global [%0], [%1], 16;" :: "r"(d), "l"(g));
}
__device__ __forceinline__ void cp_commit() {
    asm volatile("cp.async.commit_group;" ::: "memory");
}
template<int N> __device__ __forceinline__ void cp_wait() {
    asm volatile("cp.async.wait_group %0;" :: "n"(N) : "memory");
}

// ---------------- fused init: zero + conv_in + 3x wconv ----------------
// block ranges: [0, NCONV) conv_in, [NCONV, NCONV+384) wconv, rest zero.
#define NCONV  (N_PAD * 128 / 256)         // 50048
#define NWC    384                         // 98304 / 256
#define NZERO  ((N_NODES + 255) / 256)     // 391

__global__ void k_init(const float* __restrict__ x,
                       const float* __restrict__ wn1, const float* __restrict__ ws1,
                       const float* __restrict__ wn2, const float* __restrict__ ws2,
                       const float* __restrict__ wn3, const float* __restrict__ ws3)
{
    int b = blockIdx.x;
    int tid = threadIdx.x;
    if (b < NCONV) {
        int idx = b * 256 + tid;
        int n = idx >> 7;
        float v = (n < N_NODES) ? x[idx] : 0.f;
        g_a[idx] = __float2half(v);
    } else if (b < NCONV + NWC) {
        int idx = (b - NCONV) * 256 + tid;      // 0 .. 98303
        int l = idx >> 15;                      // layer 0..2
        int li = idx & 32767;
        int n = li >> 7, k = li & 127;
        const float* Wn = (l == 0) ? wn1 : (l == 1) ? wn2 : wn3;
        const float* Ws = (l == 0) ? ws1 : (l == 1) ? ws2 : ws3;
        int K    = (l == 2) ? 118 : 128;
        int dout = (l == 0) ? 128 : (l == 1) ? 118 : 103;
        float v = 0.f;
        if (k < K) {
            if (n < 128) { if (n < dout) v = Wn[k * dout + n]; }
            else { int s = n - 128; if (s < dout) v = Ws[k * dout + s]; }
        }
        __half h = __float2half(v);
        __half lo = __float2half(v - __half2float(h));
        g_bh[idx] = h;
        g_bl[idx] = lo;
    } else {
        int i = (b - NCONV - NWC) * 256 + tid;
        if (i < N_NODES) g_rowcnt[i] = 0;
        if (i < N_GRAPHS * 5) g_pool[i] = 0.f;
        if (i < N_GRAPHS) g_gcnt[i] = 0;
    }
}

// ---------------- CSR build ----------------
__global__ void k_count(const int* __restrict__ dst) {
    int e = blockIdx.x * blockDim.x + threadIdx.x;
    if (e < N_EDGES) atomicAdd(&g_rowcnt[dst[e]], 1);
}

__global__ void k_scan1() {
    __shared__ int s[SCAN_B];
    int tid = threadIdx.x;
    int gid = blockIdx.x * SCAN_B + tid;
    int v = (gid < N_NODES) ? g_rowcnt[gid] : 0;
    s[tid] = v;
    __syncthreads();
    for (int off = 1; off < SCAN_B; off <<= 1) {
        int t = (tid >= off) ? s[tid - off] : 0;
        __syncthreads();
        s[tid] += t;
        __syncthreads();
    }
    if (gid < N_NODES) g_rowptr[gid] = s[tid] - v;
    if (tid == SCAN_B - 1) g_bsum[blockIdx.x] = s[tid];
}

// scan3: each block redundantly scans the 98 block sums, then finalizes its slice
__global__ void k_scan3() {
    __shared__ int s[128];
    int tid = threadIdx.x;
    {
        int t = tid & 127;
        if (tid < 128) s[t] = (t < NB_SCAN) ? g_bsum[t] : 0;
    }
    __syncthreads();
    if (tid < 128) {
        // Hillis-Steele inclusive scan by first 128 threads (4 warps), staged
        for (int off = 1; off < 128; off <<= 1) {
            int x = (tid >= off) ? s[tid - off] : 0;
            __syncthreads();
            s[tid] += x;
            __syncthreads();
        }
    } else {
        for (int off = 1; off < 128; off <<= 1) { __syncthreads(); __syncthreads(); }
    }
    int boff = (blockIdx.x > 0) ? s[blockIdx.x - 1] : 0;   // exclusive offset
    int gid = blockIdx.x * SCAN_B + tid;
    if (gid < N_NODES) {
        int rp = g_rowptr[gid] + boff;
        g_rowptr[gid] = rp;
        g_cursor[gid] = rp;
        int c = g_rowcnt[gid];
        g_invdeg[gid] = 1.0f / (float)(c > 0 ? c : 1);
    }
}

__global__ void k_fill(const int* __restrict__ src, const int* __restrict__ dst) {
    int e = blockIdx.x * blockDim.x + threadIdx.x;
    if (e < N_EDGES) {
        int pos = atomicAdd(&g_cursor[dst[e]], 1);
        g_csr[pos] = src[e];
    }
}

// ---------------- pipelined HMMA GEMM (fp16 2-product, high occupancy) ----------------
// Per CTA: 64(m) x 64(n), 128 threads, 4 warps of 32x32 tiles.
// K=128 in 4 chunks of 32, 2-stage cp.async. ~70 regs -> 6-7 CTAs/SM = 24-28 warps.
// blockIdx.y in [0,4): n0 = by*64;  n0<128 -> Yn fp16,  else -> Ys fp32.
#define PITCH  80
#define APLANE 5120                      // 64 rows * 80
#define STAGEB 15360                     // A + Bh + Bl
#define GEMM_SMEM 30720

__global__ void __launch_bounds__(128)
k_gemm_pipe(const __half* __restrict__ a,
            const __half* __restrict__ bh, const __half* __restrict__ bl,
            __half* __restrict__ Yn, float* __restrict__ Ys)
{
    extern __shared__ char smem[];
    const int tid = threadIdx.x;
    const int m0 = blockIdx.x * 64;
    const int n0 = blockIdx.y * 64;
    const uint32_t sb = smem_u32(smem);

    const int f_row = tid >> 2;          // 0..31
    const int f_kc  = tid & 3;
    #define FILL(st, ks) do {                                                  \
        uint32_t sbase = sb + (st) * STAGEB;                                   \
        _Pragma("unroll")                                                      \
        for (int i = 0; i < 2; ++i) {                                          \
            int row = f_row + i * 32;                                          \
            uint32_t doff = row * PITCH + f_kc * 16;                           \
            size_t ga = (size_t)(m0 + row) * 128 + (ks) * 32 + f_kc * 8;       \
            size_t gb = (size_t)(n0 + row) * 128 + (ks) * 32 + f_kc * 8;       \
            cpa16(sbase + doff,              a  + ga);                         \
            cpa16(sbase + APLANE + doff,     bh + gb);                         \
            cpa16(sbase + 2 * APLANE + doff, bl + gb);                         \
        }                                                                      \
    } while (0)

    FILL(0, 0); cp_commit();
    FILL(1, 1); cp_commit();

    const int wid = tid >> 5, lane = tid & 31;
    const int wm = (wid & 1) * 32;       // warp m offset
    const int wn = (wid >> 1) * 32;      // warp n offset

    float acc[2][4][4];
    #pragma unroll
    for (int mf = 0; mf < 2; ++mf)
        #pragma unroll
        for (int nf = 0; nf < 4; ++nf)
            #pragma unroll
            for (int q = 0; q < 4; ++q) acc[mf][nf][q] = 0.f;

    const uint32_t aL = (uint32_t)(lane & 15) * PITCH + (lane >> 4) * 16;
    const uint32_t bL = (uint32_t)((lane & 7) + ((lane >> 4) << 3)) * PITCH
                        + ((lane >> 3) & 1) * 16;

    #pragma unroll
    for (int ks = 0; ks < 4; ++ks) {
        cp_wait<1>();
        __syncthreads();
        const uint32_t st = sb + (ks & 1) * STAGEB;
        #pragma unroll
        for (int kk = 0; kk < 2; ++kk) {
            const uint32_t kb = kk * 32;
            uint32_t A4[2][4], Bh4[2][4], Bl4[2][4];
            #pragma unroll
            for (int mf = 0; mf < 2; ++mf)
                ldsm4(A4[mf], st + (uint32_t)(wm + mf * 16) * PITCH + aL + kb);
            #pragma unroll
            for (int nq = 0; nq < 2; ++nq) {
                uint32_t bbase = st + APLANE + (uint32_t)(wn + nq * 16) * PITCH + bL + kb;
                ldsm4(Bh4[nq], bbase);
                ldsm4(Bl4[nq], bbase + APLANE);
            }
            #pragma unroll
            for (int nq = 0; nq < 2; ++nq)
                #pragma unroll
                for (int mf = 0; mf < 2; ++mf) {
                    float* c0 = acc[mf][2 * nq];
                    float* c1 = acc[mf][2 * nq + 1];
                    mma16816h(c0, A4[mf], Bh4[nq][0], Bh4[nq][1]);
                    mma16816h(c0, A4[mf], Bl4[nq][0], Bl4[nq][1]);
                    mma16816h(c1, A4[mf], Bh4[nq][2], Bh4[nq][3]);
                    mma16816h(c1, A4[mf], Bl4[nq][2], Bl4[nq][3]);
                }
        }
        __syncthreads();
        if (ks + 2 < 4) FILL(ks & 1, ks + 2);
        cp_commit();
    }

    // ---- epilogue ----
    const int gid = lane >> 2, tig = lane & 3;
    if (n0 < 128) {
        #pragma unroll
        for (int mf = 0; mf < 2; ++mf) {
            int r = m0 + wm + mf * 16 + gid;
            #pragma unroll
            for (int nf = 0; nf < 4; ++nf) {
                int col = n0 + wn + nf * 8 + tig * 2;
                *(__half2*)&Yn[(size_t)r * 128 + col] =
                    __floats2half2_rn(acc[mf][nf][0], acc[mf][nf][1]);
                *(__half2*)&Yn[(size_t)(r + 8) * 128 + col] =
                    __floats2half2_rn(acc[mf][nf][2], acc[mf][nf][3]);
            }
        }
    } else {
        #pragma unroll
        for (int mf = 0; mf < 2; ++mf) {
            int r = m0 + wm + mf * 16 + gid;
            #pragma unroll
            for (int nf = 0; nf < 4; ++nf) {
                int col = (n0 - 128) + wn + nf * 8 + tig * 2;
                *(float2*)&Ys[(size_t)r * 128 + col] =
                    make_float2(acc[mf][nf][0], acc[mf][nf][1]);
                *(float2*)&Ys[(size_t)(r + 8) * 128 + col] =
                    make_float2(acc[mf][nf][2], acc[mf][nf][3]);
            }
        }
    }
}

// ---------------- fused aggregation + epilogue ----------------
// Half-warp (16 lanes) per node, uint4 per lane.
template<int DOUT, int RELU, int OUTH>
__global__ void k_agg(const __half* __restrict__ Yn, const float* __restrict__ Ys,
                      const float* __restrict__ bias,
                      __half* __restrict__ oh, float* __restrict__ of)
{
    int node = (int)((blockIdx.x * blockDim.x + threadIdx.x) >> 4);
    int l = threadIdx.x & 15;
    if (node >= N_NODES) return;
    int beg = g_rowptr[node];
    int cnt = g_rowcnt[node];
    const int c = l * 8;

    float s[8];
    #pragma unroll
    for (int t = 0; t < 8; ++t) s[t] = 0.f;

    int j = 0;
    for (; j + 2 <= cnt; j += 2) {
        int i0 = g_csr[beg + j];
        int i1 = g_csr[beg + j + 1];
        uint4 u0 = *(const uint4*)(Yn + (size_t)i0 * 128 + c);
        uint4 u1 = *(const uint4*)(Yn + (size_t)i1 * 128 + c);
        const __half2* h0 = (const __half2*)&u0;
        const __half2* h1 = (const __half2*)&u1;
        #pragma unroll
        for (int q = 0; q < 4; ++q) {
            float2 f0 = __half22float2(h0[q]);
            float2 f1 = __half22float2(h1[q]);
            s[2 * q]     += f0.x + f1.x;
            s[2 * q + 1] += f0.y + f1.y;
        }
    }
    if (j < cnt) {
        int i0 = g_csr[beg + j];
        uint4 u0 = *(const uint4*)(Yn + (size_t)i0 * 128 + c);
        const __half2* h0 = (const __half2*)&u0;
        #pragma unroll
        for (int q = 0; q < 4; ++q) {
            float2 f0 = __half22float2(h0[q]);
            s[2 * q]     += f0.x;
            s[2 * q + 1] += f0.y;
        }
    }

    float inv = g_invdeg[node];
    float4 self0 = *(const float4*)(Ys + (size_t)node * 128 + c);
    float4 self1 = *(const float4*)(Ys + (size_t)node * 128 + c + 4);
    float selfv[8] = { self0.x, self0.y, self0.z, self0.w,
                       self1.x, self1.y, self1.z, self1.w };
    float v[8];
    #pragma unroll
    for (int t = 0; t < 8; ++t) {
        int cc = c + t;
        if (cc < DOUT) {
            float x = selfv[t] + s[t] * inv + bias[cc];
            v[t] = RELU ? fmaxf(x, 0.f) : x;
        } else {
            v[t] = 0.f;
        }
    }

    if (OUTH) {
        union { __half2 h2[4]; uint4 u; } uo;
        #pragma unroll
        for (int q = 0; q < 4; ++q)
            uo.h2[q] = __floats2half2_rn(v[2 * q], v[2 * q + 1]);
        *(uint4*)(oh + (size_t)node * 128 + c) = uo.u;
    } else {
        if (c < 104) {
            *(float4*)(of + (size_t)node * 104 + c) =
                make_float4(v[0], v[1], v[2], v[3]);
            *(float4*)(of + (size_t)node * 104 + c + 4) =
                make_float4(v[4], v[5], v[6], v[7]);
        }
    }
}

// ---------------- layer 4: tiny GEMM (N=10) ----------------
__global__ void k_gemm4(const float* __restrict__ h3,
                        const float* __restrict__ ws4, const float* __restrict__ wn4,
                        float* __restrict__ hs4, float* __restrict__ hn4)
{
    __shared__ float sW[1040];
    int tid = threadIdx.x;
    for (int idx = tid; idx < 1040; idx += 256) {
        int k = idx / 10, cc = idx % 10;
        sW[idx] = (k < 103) ? ((cc < 5) ? ws4[k * 5 + cc] : wn4[k * 5 + (cc - 5)]) : 0.f;
    }
    __syncthreads();
    int node = blockIdx.x * 16 + (tid >> 4);
    int cc = tid & 15;
    if (node >= N_NODES || cc >= 10) return;
    const float4* row = (const float4*)(h3 + (size_t)node * 104);
    float acc = 0.f;
    #pragma unroll 13
    for (int kc = 0; kc < 26; ++kc) {
        float4 r = __ldg(row + kc);
        int kb = kc * 40;
        acc += r.x * sW[kb + cc] + r.y * sW[kb + 10 + cc]
             + r.z * sW[kb + 20 + cc] + r.w * sW[kb + 30 + cc];
    }
    if (cc < 5) hs4[node * 8 + cc] = acc;
    else        hn4[node * 8 + (cc - 5)] = acc;
}

// layer 4 aggregation fused with graph pooling
__global__ void k_agg4pool(const float* __restrict__ hn4, const float* __restrict__ hs4,
                           const float* __restrict__ b4, const int* __restrict__ gids)
{
    int n = blockIdx.x * blockDim.x + threadIdx.x;
    if (n >= N_NODES) return;
    int beg = g_rowptr[n], cnt = g_rowcnt[n];
    float a0 = 0.f, a1 = 0.f, a2 = 0.f, a3 = 0.f, a4 = 0.f;
    for (int j = 0; j < cnt; ++j) {
        const float* r = hn4 + (size_t)g_csr[beg + j] * 8;
        a0 += __ldg(r + 0); a1 += __ldg(r + 1); a2 += __ldg(r + 2);
        a3 += __ldg(r + 3); a4 += __ldg(r + 4);
    }
    float inv = g_invdeg[n];
    int g = gids[n];
    atomicAdd(&g_gcnt[g], 1);
    atomicAdd(&g_pool[g * 5 + 0], hs4[n * 8 + 0] + inv * a0 + b4[0]);
    atomicAdd(&g_pool[g * 5 + 1], hs4[n * 8 + 1] + inv * a1 + b4[1]);
    atomicAdd(&g_pool[g * 5 + 2], hs4[n * 8 + 2] + inv * a2 + b4[2]);
    atomicAdd(&g_pool[g * 5 + 3], hs4[n * 8 + 3] + inv * a3 + b4[3]);
    atomicAdd(&g_pool[g * 5 + 4], hs4[n * 8 + 4] + inv * a4 + b4[4]);
}

__global__ void k_final(float* __restrict__ out) {
    int i = blockIdx.x * blockDim.x + threadIdx.x;
    if (i < N_GRAPHS * 5) {
        int g = i / 5;
        int c = g_gcnt[g];
        out[i] = g_pool[i] / (float)(c > 0 ? c : 1);
    }
}

// ---------------- launch ----------------
extern "C" void kernel_launch(void* const* d_in, const int* in_sizes, int n_in,
                              void* d_out, int out_size)
{
    const float* in_feat = (const float*)d_in[0];
    const int*   src     = (const int*)d_in[1];
    const int*   dst     = (const int*)d_in[2];
    const int*   gids    = (const int*)d_in[3];
    const float* ws[4] = { (const float*)d_in[4],  (const float*)d_in[7],
                           (const float*)d_in[10], (const float*)d_in[13] };
    const float* wn[4] = { (const float*)d_in[5],  (const float*)d_in[8],
                           (const float*)d_in[11], (const float*)d_in[14] };
    const float* bs[4] = { (const float*)d_in[6],  (const float*)d_in[9],
                           (const float*)d_in[12], (const float*)d_in[15] };

    __half *a, *bh, *bl, *yn;
    float *ys, *h3;
    cudaGetSymbolAddress((void**)&a,  g_a);
    cudaGetSymbolAddress((void**)&bh, g_bh);
    cudaGetSymbolAddress((void**)&bl, g_bl);
    cudaGetSymbolAddress((void**)&yn, g_yn);
    cudaGetSymbolAddress((void**)&ys, g_ys);
    cudaGetSymbolAddress((void**)&h3, g_h3);
    float* hs4 = ys;                 // g_ys free after agg3
    float* hn4 = ys + 800000;

    cudaFuncSetAttribute(k_gemm_pipe, cudaFuncAttributeMaxDynamicSharedMemorySize, GEMM_SMEM);

    const int TB = 256;
    const dim3 gemmGrid(N_PAD / 64, 4);                   // 1564 x 4
    const int aggBlocks = (N_NODES * 16 + TB - 1) / TB;   // half-warp per node

    // init (zero + conv_in + wconv x3)
    k_init<<<NCONV + NWC + NZERO, TB>>>(in_feat, wn[0], ws[0], wn[1], ws[1],
                                        wn[2], ws[2]);                        // 0
    k_count<<<(N_EDGES + TB - 1) / TB, TB>>>(dst);                            // 1
    k_scan1<<<NB_SCAN, SCAN_B>>>();                                           // 2
    k_gemm_pipe<<<gemmGrid, 128, GEMM_SMEM>>>(a, bh, bl, yn, ys);             // 3 (profiled)
    k_scan3<<<NB_SCAN, SCAN_B>>>();                                           // 4
    k_fill<<<(N_EDGES + TB - 1) / TB, TB>>>(src, dst);                        // 5

    // layer 1 epilogue -> fp16 activations for layer 2
    k_agg<128, 1, 1><<<aggBlocks, TB>>>(yn, ys, bs[0], a, nullptr);           // 6
    // layer 2
    k_gemm_pipe<<<gemmGrid, 128, GEMM_SMEM>>>(a, bh + 32768, bl + 32768, yn, ys); // 7
    k_agg<118, 1, 1><<<aggBlocks, TB>>>(yn, ys, bs[1], a, nullptr);           // 8
    // layer 3
    k_gemm_pipe<<<gemmGrid, 128, GEMM_SMEM>>>(a, bh + 65536, bl + 65536, yn, ys); // 9
    k_agg<103, 1, 0><<<aggBlocks, TB>>>(yn, ys, bs[2], nullptr, h3);          // 10
    // layer 4 (SIMT, tiny) + pooling
    k_gemm4<<<(N_NODES + 15) / 16, TB>>>(h3, ws[3], wn[3], hs4, hn4);         // 11
    k_agg4pool<<<(N_NODES + TB - 1) / TB, TB>>>(hn4, hs4, bs[3], gids);       // 12
    k_final<<<1, 512>>>((float*)d_out);                                       // 13
}

// round 13
// speedup vs baseline: 1.1545x; 1.1545x over previous
#include <cuda_runtime.h>
#include <cuda_bf16.h>
#include <cuda_fp16.h>
#include <cstdint>

#define N_NODES  100000
#define N_PAD    100096          // 782 * 128
#define N_EDGES  1600000
#define N_GRAPHS 100
#define SCAN_B   1024
#define NB_SCAN  98

// ---------------- scratch (static __device__ allocations only) ----------------
__device__ __half g_a [N_PAD * 128];          // activations, fp16, pitch 128
__device__ __half g_bh[3 * 256 * 128];        // B hi planes, layer l at offset l*32768
__device__ __half g_bl[3 * 256 * 128];        // B lo planes (fp16 residual)
__device__ __half g_yn[N_PAD * 128];          // neighbor-transform out (fp16)
__device__ float  g_ys[N_PAD * 128];          // self-transform out (fp32)
__device__ float  g_h3[N_NODES * 104];        // layer-3 activation (fp32, pitch 104)
__device__ float g_invdeg[N_NODES];
__device__ int   g_rowcnt[N_NODES];
__device__ int   g_rowptr[N_NODES];
__device__ int   g_cursor[N_NODES];
__device__ int   g_csr[N_EDGES];
__device__ int   g_bsum[128];
__device__ float g_pool[N_GRAPHS * 5];
__device__ int   g_gcnt[N_GRAPHS];

// ---------------- PTX helpers ----------------
__device__ __forceinline__ uint32_t smem_u32(const void* p) {
    uint32_t a;
    asm("{ .reg .u64 t; cvta.to.shared.u64 t, %1; cvt.u32.u64 %0, t; }" : "=r"(a) : "l"(p));
    return a;
}
__device__ __forceinline__ void ldsm4(uint32_t* r, uint32_t addr) {
    asm volatile("ldmatrix.sync.aligned.m8n8.x4.shared.b16 {%0,%1,%2,%3}, [%4];"
                 : "=r"(r[0]), "=r"(r[1]), "=r"(r[2]), "=r"(r[3]) : "r"(addr));
}
__device__ __forceinline__ void mma16816h(float* c, const uint32_t* a,
                                          uint32_t b0, uint32_t b1) {
    asm volatile(
        "mma.sync.aligned.m16n8k16.row.col.f32.f16.f16.f32 "
        "{%0,%1,%2,%3}, {%4,%5,%6,%7}, {%8,%9}, {%0,%1,%2,%3};"
        : "+f"(c[0]), "+f"(c[1]), "+f"(c[2]), "+f"(c[3])
        : "r"(a[0]), "r"(a[1]), "r"(a[2]), "r"(a[3]), "r"(b0), "r"(b1));
}
__device__ __forceinline__ void cpa16(uint32_t d, const void* g) {
    asm volatile("cp.async.cg.shared.global [%0], [%1], 16;" :: "r"(d), "l"(g));
}
__device__ __forceinline__ void cp_commit() {
    asm volatile("cp.async.commit_group;" ::: "memory");
}
template<int N> __device__ __forceinline__ void cp_wait() {
    asm volatile("cp.async.wait_group %0;" :: "n"(N) : "memory");
}

// ---------------- fused init: zero + conv_in + 3x wconv ----------------
#define NCONV  (N_PAD * 128 / 256)         // 50048
#define NWC    384                         // 98304 / 256
#define NZERO  ((N_NODES + 255) / 256)     // 391

__global__ void k_init(const float* __restrict__ x,
                       const float* __restrict__ wn1, const float* __restrict__ ws1,
                       const float* __restrict__ wn2, const float* __restrict__ ws2,
                       const float* __restrict__ wn3, const float* __restrict__ ws3)
{
    int b = blockIdx.x;
    int tid = threadIdx.x;
    if (b < NCONV) {
        int idx = b * 256 + tid;
        int n = idx >> 7;
        float v = (n < N_NODES) ? x[idx] : 0.f;
        g_a[idx] = __float2half(v);
    } else if (b < NCONV + NWC) {
        int idx = (b - NCONV) * 256 + tid;      // 0 .. 98303
        int l = idx >> 15;                      // layer 0..2
        int li = idx & 32767;
        int n = li >> 7, k = li & 127;
        const float* Wn = (l == 0) ? wn1 : (l == 1) ? wn2 : wn3;
        const float* Ws = (l == 0) ? ws1 : (l == 1) ? ws2 : ws3;
        int K    = (l == 2) ? 118 : 128;
        int dout = (l == 0) ? 128 : (l == 1) ? 118 : 103;
        float v = 0.f;
        if (k < K) {
            if (n < 128) { if (n < dout) v = Wn[k * dout + n]; }
            else { int s = n - 128; if (s < dout) v = Ws[k * dout + s]; }
        }
        __half h = __float2half(v);
        __half lo = __float2half(v - __half2float(h));
        g_bh[idx] = h;
        g_bl[idx] = lo;
    } else {
        int i = (b - NCONV - NWC) * 256 + tid;
        if (i < N_NODES) g_rowcnt[i] = 0;
        if (i < N_GRAPHS * 5) g_pool[i] = 0.f;
        if (i < N_GRAPHS) g_gcnt[i] = 0;
    }
}

// ---------------- CSR build ----------------
__global__ void k_count(const int* __restrict__ dst) {
    int e = blockIdx.x * blockDim.x + threadIdx.x;
    if (e < N_EDGES) atomicAdd(&g_rowcnt[dst[e]], 1);
}

__global__ void k_scan1() {
    __shared__ int s[SCAN_B];
    int tid = threadIdx.x;
    int gid = blockIdx.x * SCAN_B + tid;
    int v = (gid < N_NODES) ? g_rowcnt[gid] : 0;
    s[tid] = v;
    __syncthreads();
    for (int off = 1; off < SCAN_B; off <<= 1) {
        int t = (tid >= off) ? s[tid - off] : 0;
        __syncthreads();
        s[tid] += t;
        __syncthreads();
    }
    if (gid < N_NODES) g_rowptr[gid] = s[tid] - v;
    if (tid == SCAN_B - 1) g_bsum[blockIdx.x] = s[tid];
}

// scan3: each block redundantly scans the 98 block sums, then finalizes its slice
__global__ void k_scan3() {
    __shared__ int s[128];
    int tid = threadIdx.x;
    if (tid < 128) s[tid] = (tid < NB_SCAN) ? g_bsum[tid] : 0;
    __syncthreads();
    if (tid < 128) {
        for (int off = 1; off < 128; off <<= 1) {
            int x = (tid >= off) ? s[tid - off] : 0;
            __syncthreads();
            s[tid] += x;
            __syncthreads();
        }
    } else {
        for (int off = 1; off < 128; off <<= 1) { __syncthreads(); __syncthreads(); }
    }
    int boff = (blockIdx.x > 0) ? s[blockIdx.x - 1] : 0;   // exclusive offset
    int gid = blockIdx.x * SCAN_B + tid;
    if (gid < N_NODES) {
        int rp = g_rowptr[gid] + boff;
        g_rowptr[gid] = rp;
        g_cursor[gid] = rp;
        int c = g_rowcnt[gid];
        g_invdeg[gid] = 1.0f / (float)(c > 0 ? c : 1);
    }
}

__global__ void k_fill(const int* __restrict__ src, const int* __restrict__ dst) {
    int e = blockIdx.x * blockDim.x + threadIdx.x;
    if (e < N_EDGES) {
        int pos = atomicAdd(&g_cursor[dst[e]], 1);
        g_csr[pos] = src[e];
    }
}

// ---------------- pipelined HMMA GEMM (fp16 2-product, R8 config) ----------------
// Per CTA: 128(m) x 128(n), 256 threads, 8 warps of 64x32 tiles, 2 CTAs/SM.
// K=128 in 4 chunks of 32, 2-stage cp.async.
// blockIdx.y = 0: B rows [0,128) (Wn) -> Yn fp16;  = 1: B rows [128,256) -> Ys fp32.
#define PITCH  80
#define PLANE  10240
#define STAGEB 30720                     // A + Bh + Bl
#define GEMM_SMEM 61440

__global__ void __launch_bounds__(256, 2)
k_gemm_pipe(const __half* __restrict__ a,
            const __half* __restrict__ bh, const __half* __restrict__ bl,
            __half* __restrict__ Yn, float* __restrict__ Ys)
{
    extern __shared__ char smem[];
    const int tid = threadIdx.x;
    const int m0 = blockIdx.x * 128;
    const int n0 = blockIdx.y * 128;
    const uint32_t sb = smem_u32(smem);

    const int f_row = tid >> 2;          // 64 rows per pass
    const int f_kc  = tid & 3;
    #define FILL(st, ks) do {                                                  \
        uint32_t sbase = sb + (st) * STAGEB;                                   \
        _Pragma("unroll")                                                      \
        for (int i = 0; i < 2; ++i) {                                          \
            int row = f_row + i * 64;                                          \
            uint32_t doff = row * PITCH + f_kc * 16;                           \
            size_t ga = (size_t)(m0 + row) * 128 + (ks) * 32 + f_kc * 8;       \
            size_t gb = (size_t)(n0 + row) * 128 + (ks) * 32 + f_kc * 8;       \
            cpa16(sbase + doff,             a  + ga);                          \
            cpa16(sbase + PLANE + doff,     bh + gb);                          \
            cpa16(sbase + 2 * PLANE + doff, bl + gb);                          \
        }                                                                      \
    } while (0)

    FILL(0, 0); cp_commit();
    FILL(1, 1); cp_commit();

    const int wid = tid >> 5, lane = tid & 31;
    const int wm  = (wid & 1) * 64;
    const int wn2 = (wid >> 1) * 32;

    float acc[4][4][4];
    #pragma unroll
    for (int mf = 0; mf < 4; ++mf)
        #pragma unroll
        for (int nf = 0; nf < 4; ++nf)
            #pragma unroll
            for (int q = 0; q < 4; ++q) acc[mf][nf][q] = 0.f;

    const uint32_t aL = (uint32_t)(lane & 15) * PITCH + (lane >> 4) * 16;
    const uint32_t bL = (uint32_t)((lane & 7) + ((lane >> 4) << 3)) * PITCH
                        + ((lane >> 3) & 1) * 16;

    #pragma unroll
    for (int ks = 0; ks < 4; ++ks) {
        cp_wait<1>();
        __syncthreads();
        const uint32_t st = sb + (ks & 1) * STAGEB;
        #pragma unroll
        for (int kk = 0; kk < 2; ++kk) {
            const uint32_t kb = kk * 32;
            uint32_t A4[4][4], Bh4[2][4], Bl4[2][4];
            #pragma unroll
            for (int mf = 0; mf < 4; ++mf)
                ldsm4(A4[mf], st + (uint32_t)(wm + mf * 16) * PITCH + aL + kb);
            #pragma unroll
            for (int nq = 0; nq < 2; ++nq) {
                uint32_t bbase = st + PLANE + (uint32_t)(wn2 + nq * 16) * PITCH + bL + kb;
                ldsm4(Bh4[nq], bbase);
                ldsm4(Bl4[nq], bbase + PLANE);
            }
            #pragma unroll
            for (int nq = 0; nq < 2; ++nq)
                #pragma unroll
                for (int mf = 0; mf < 4; ++mf) {
                    float* c0 = acc[mf][2 * nq];
                    float* c1 = acc[mf][2 * nq + 1];
                    mma16816h(c0, A4[mf], Bh4[nq][0], Bh4[nq][1]);
                    mma16816h(c0, A4[mf], Bl4[nq][0], Bl4[nq][1]);
                    mma16816h(c1, A4[mf], Bh4[nq][2], Bh4[nq][3]);
                    mma16816h(c1, A4[mf], Bl4[nq][2], Bl4[nq][3]);
                }
        }
        __syncthreads();
        if (ks + 2 < 4) FILL(ks & 1, ks + 2);
        cp_commit();
    }

    // ---- epilogue ----
    const int gid = lane >> 2, tig = lane & 3;
    if (blockIdx.y == 0) {
        #pragma unroll
        for (int mf = 0; mf < 4; ++mf) {
            int r = m0 + wm + mf * 16 + gid;
            #pragma unroll
            for (int nf = 0; nf < 4; ++nf) {
                int col = wn2 + nf * 8 + tig * 2;
                *(__half2*)&Yn[(size_t)r * 128 + col] =
                    __floats2half2_rn(acc[mf][nf][0], acc[mf][nf][1]);
                *(__half2*)&Yn[(size_t)(r + 8) * 128 + col] =
                    __floats2half2_rn(acc[mf][nf][2], acc[mf][nf][3]);
            }
        }
    } else {
        #pragma unroll
        for (int mf = 0; mf < 4; ++mf) {
            int r = m0 + wm + mf * 16 + gid;
            #pragma unroll
            for (int nf = 0; nf < 4; ++nf) {
                int col = wn2 + nf * 8 + tig * 2;
                *(float2*)&Ys[(size_t)r * 128 + col] =
                    make_float2(acc[mf][nf][0], acc[mf][nf][1]);
                *(float2*)&Ys[(size_t)(r + 8) * 128 + col] =
                    make_float2(acc[mf][nf][2], acc[mf][nf][3]);
            }
        }
    }
}

// ---------------- fused aggregation + epilogue ----------------
// Half-warp (16 lanes) per node, uint4 per lane, 4 edges in flight.
template<int DOUT, int RELU, int OUTH>
__global__ void k_agg(const __half* __restrict__ Yn, const float* __restrict__ Ys,
                      const float* __restrict__ bias,
                      __half* __restrict__ oh, float* __restrict__ of)
{
    int node = (int)((blockIdx.x * blockDim.x + threadIdx.x) >> 4);
    int l = threadIdx.x & 15;
    if (node >= N_NODES) return;
    int beg = g_rowptr[node];
    int cnt = g_rowcnt[node];
    const int c = l * 8;

    float s[8];
    #pragma unroll
    for (int t = 0; t < 8; ++t) s[t] = 0.f;

    int j = 0;
    for (; j + 4 <= cnt; j += 4) {
        int i0 = g_csr[beg + j];
        int i1 = g_csr[beg + j + 1];
        int i2 = g_csr[beg + j + 2];
        int i3 = g_csr[beg + j + 3];
        uint4 u0 = *(const uint4*)(Yn + (size_t)i0 * 128 + c);
        uint4 u1 = *(const uint4*)(Yn + (size_t)i1 * 128 + c);
        uint4 u2 = *(const uint4*)(Yn + (size_t)i2 * 128 + c);
        uint4 u3 = *(const uint4*)(Yn + (size_t)i3 * 128 + c);
        const __half2* h0 = (const __half2*)&u0;
        const __half2* h1 = (const __half2*)&u1;
        const __half2* h2 = (const __half2*)&u2;
        const __half2* h3 = (const __half2*)&u3;
        #pragma unroll
        for (int q = 0; q < 4; ++q) {
            float2 f0 = __half22float2(h0[q]);
            float2 f1 = __half22float2(h1[q]);
            float2 f2 = __half22float2(h2[q]);
            float2 f3 = __half22float2(h3[q]);
            s[2 * q]     += (f0.x + f1.x) + (f2.x + f3.x);
            s[2 * q + 1] += (f0.y + f1.y) + (f2.y + f3.y);
        }
    }
    for (; j < cnt; ++j) {
        int i0 = g_csr[beg + j];
        uint4 u0 = *(const uint4*)(Yn + (size_t)i0 * 128 + c);
        const __half2* h0 = (const __half2*)&u0;
        #pragma unroll
        for (int q = 0; q < 4; ++q) {
            float2 f0 = __half22float2(h0[q]);
            s[2 * q]     += f0.x;
            s[2 * q + 1] += f0.y;
        }
    }

    float inv = g_invdeg[node];
    float4 self0 = *(const float4*)(Ys + (size_t)node * 128 + c);
    float4 self1 = *(const float4*)(Ys + (size_t)node * 128 + c + 4);
    float selfv[8] = { self0.x, self0.y, self0.z, self0.w,
                       self1.x, self1.y, self1.z, self1.w };
    float v[8];
    #pragma unroll
    for (int t = 0; t < 8; ++t) {
        int cc = c + t;
        if (cc < DOUT) {
            float x = selfv[t] + s[t] * inv + bias[cc];
            v[t] = RELU ? fmaxf(x, 0.f) : x;
        } else {
            v[t] = 0.f;
        }
    }

    if (OUTH) {
        union { __half2 h2[4]; uint4 u; } uo;
        #pragma unroll
        for (int q = 0; q < 4; ++q)
            uo.h2[q] = __floats2half2_rn(v[2 * q], v[2 * q + 1]);
        *(uint4*)(oh + (size_t)node * 128 + c) = uo.u;
    } else {
        if (c < 104) {
            *(float4*)(of + (size_t)node * 104 + c) =
                make_float4(v[0], v[1], v[2], v[3]);
            *(float4*)(of + (size_t)node * 104 + c + 4) =
                make_float4(v[4], v[5], v[6], v[7]);
        }
    }
}

// ---------------- layer 4: tiny GEMM (N=10) ----------------
__global__ void k_gemm4(const float* __restrict__ h3,
                        const float* __restrict__ ws4, const float* __restrict__ wn4,
                        float* __restrict__ hs4, float* __restrict__ hn4)
{
    __shared__ float sW[1040];
    int tid = threadIdx.x;
    for (int idx = tid; idx < 1040; idx += 256) {
        int k = idx / 10, cc = idx % 10;
        sW[idx] = (k < 103) ? ((cc < 5) ? ws4[k * 5 + cc] : wn4[k * 5 + (cc - 5)]) : 0.f;
    }
    __syncthreads();
    int node = blockIdx.x * 16 + (tid >> 4);
    int cc = tid & 15;
    if (node >= N_NODES || cc >= 10) return;
    const float4* row = (const float4*)(h3 + (size_t)node * 104);
    float acc = 0.f;
    #pragma unroll 13
    for (int kc = 0; kc < 26; ++kc) {
        float4 r = __ldg(row + kc);
        int kb = kc * 40;
        acc += r.x * sW[kb + cc] + r.y * sW[kb + 10 + cc]
             + r.z * sW[kb + 20 + cc] + r.w * sW[kb + 30 + cc];
    }
    if (cc < 5) hs4[node * 8 + cc] = acc;
    else        hn4[node * 8 + (cc - 5)] = acc;
}

// layer 4 aggregation fused with graph pooling
__global__ void k_agg4pool(const float* __restrict__ hn4, const float* __restrict__ hs4,
                           const float* __restrict__ b4, const int* __restrict__ gids)
{
    int n = blockIdx.x * blockDim.x + threadIdx.x;
    if (n >= N_NODES) return;
    int beg = g_rowptr[n], cnt = g_rowcnt[n];
    float a0 = 0.f, a1 = 0.f, a2 = 0.f, a3 = 0.f, a4 = 0.f;
    for (int j = 0; j < cnt; ++j) {
        const float* r = hn4 + (size_t)g_csr[beg + j] * 8;
        a0 += __ldg(r + 0); a1 += __ldg(r + 1); a2 += __ldg(r + 2);
        a3 += __ldg(r + 3); a4 += __ldg(r + 4);
    }
    float inv = g_invdeg[n];
    int g = gids[n];
    atomicAdd(&g_gcnt[g], 1);
    atomicAdd(&g_pool[g * 5 + 0], hs4[n * 8 + 0] + inv * a0 + b4[0]);
    atomicAdd(&g_pool[g * 5 + 1], hs4[n * 8 + 1] + inv * a1 + b4[1]);
    atomicAdd(&g_pool[g * 5 + 2], hs4[n * 8 + 2] + inv * a2 + b4[2]);
    atomicAdd(&g_pool[g * 5 + 3], hs4[n * 8 + 3] + inv * a3 + b4[3]);
    atomicAdd(&g_pool[g * 5 + 4], hs4[n * 8 + 4] + inv * a4 + b4[4]);
}

__global__ void k_final(float* __restrict__ out) {
    int i = blockIdx.x * blockDim.x + threadIdx.x;
    if (i < N_GRAPHS * 5) {
        int g = i / 5;
        int c = g_gcnt[g];
        out[i] = g_pool[i] / (float)(c > 0 ? c : 1);
    }
}

// ---------------- launch ----------------
extern "C" void kernel_launch(void* const* d_in, const int* in_sizes, int n_in,
                              void* d_out, int out_size)
{
    const float* in_feat = (const float*)d_in[0];
    const int*   src     = (const int*)d_in[1];
    const int*   dst     = (const int*)d_in[2];
    const int*   gids    = (const int*)d_in[3];
    const float* ws[4] = { (const float*)d_in[4],  (const float*)d_in[7],
                           (const float*)d_in[10], (const float*)d_in[13] };
    const float* wn[4] = { (const float*)d_in[5],  (const float*)d_in[8],
                           (const float*)d_in[11], (const float*)d_in[14] };
    const float* bs[4] = { (const float*)d_in[6],  (const float*)d_in[9],
                           (const float*)d_in[12], (const float*)d_in[15] };

    __half *a, *bh, *bl, *yn;
    float *ys, *h3;
    cudaGetSymbolAddress((void**)&a,  g_a);
    cudaGetSymbolAddress((void**)&bh, g_bh);
    cudaGetSymbolAddress((void**)&bl, g_bl);
    cudaGetSymbolAddress((void**)&yn, g_yn);
    cudaGetSymbolAddress((void**)&ys, g_ys);
    cudaGetSymbolAddress((void**)&h3, g_h3);
    float* hs4 = ys;                 // g_ys free after agg3
    float* hn4 = ys + 800000;

    cudaFuncSetAttribute(k_gemm_pipe, cudaFuncAttributeMaxDynamicSharedMemorySize, GEMM_SMEM);

    // side stream + fork/join events, created once outside any capture
    static cudaStream_t s1 = nullptr;
    static cudaEvent_t  e0 = nullptr, e1 = nullptr;
    if (s1 == nullptr) {
        cudaStreamCreateWithFlags(&s1, cudaStreamNonBlocking);
        cudaEventCreateWithFlags(&e0, cudaEventDisableTiming);
        cudaEventCreateWithFlags(&e1, cudaEventDisableTiming);
    }

    const int TB = 256;
    const dim3 gemmGrid(N_PAD / 128, 2);                  // 782 x 2
    const int aggBlocks = (N_NODES * 16 + TB - 1) / TB;   // half-warp per node

    // idx0: init (zero + conv_in + wconv x3) on main stream
    k_init<<<NCONV + NWC + NZERO, TB>>>(in_feat, wn[0], ws[0], wn[1], ws[1],
                                        wn[2], ws[2]);
    cudaEventRecord(e0, 0);
    cudaStreamWaitEvent(s1, e0, 0);

    // CSR build on side stream, overlapping gemm1
    k_count<<<(N_EDGES + TB - 1) / TB, TB, 0, s1>>>(dst);                    // idx1
    k_scan1<<<NB_SCAN, SCAN_B, 0, s1>>>();                                   // idx2
    // idx3 (profiled): layer-1 GEMM on main stream, depends only on init
    k_gemm_pipe<<<gemmGrid, TB, GEMM_SMEM>>>(a, bh, bl, yn, ys);
    k_scan3<<<NB_SCAN, SCAN_B, 0, s1>>>();                                   // idx4
    k_fill<<<(N_EDGES + TB - 1) / TB, TB, 0, s1>>>(src, dst);                // idx5
    cudaEventRecord(e1, s1);
    cudaStreamWaitEvent(0, e1, 0);

    // layer 1 epilogue -> fp16 activations for layer 2
    k_agg<128, 1, 1><<<aggBlocks, TB>>>(yn, ys, bs[0], a, nullptr);          // idx6
    // layer 2
    k_gemm_pipe<<<gemmGrid, TB, GEMM_SMEM>>>(a, bh + 32768, bl + 32768, yn, ys); // idx7
    k_agg<118, 1, 1><<<aggBlocks, TB>>>(yn, ys, bs[1], a, nullptr);          // idx8
    // layer 3
    k_gemm_pipe<<<gemmGrid, TB, GEMM_SMEM>>>(a, bh + 65536, bl + 65536, yn, ys); // idx9
    k_agg<103, 1, 0><<<aggBlocks, TB>>>(yn, ys, bs[2], nullptr, h3);         // idx10
    // layer 4 (SIMT, tiny) + pooling
    k_gemm4<<<(N_NODES + 15) / 16, TB>>>(h3, ws[3], wn[3], hs4, hn4);        // idx11
    k_agg4pool<<<(N_NODES + TB - 1) / TB, TB>>>(hn4, hs4, bs[3], gids);      // idx12
    k_final<<<1, 512>>>((float*)d_out);                                      // idx13
}

// round 14
// speedup vs baseline: 1.1777x; 1.0201x over previous
#include <cuda_runtime.h>
#include <cuda_bf16.h>
#include <cuda_fp16.h>
#include <cstdint>

#define N_NODES  100000
#define N_PAD    100096          // 782 * 128
#define N_EDGES  1600000
#define N_GRAPHS 100
#define SCAN_B   1024
#define NB_SCAN  98

// ---------------- scratch (static __device__ allocations only) ----------------
__device__ __half g_a [N_PAD * 128];          // activations, fp16, pitch 128
__device__ __half g_bh[3 * 256 * 128];        // B hi planes, layer l at offset l*32768
__device__ __half g_bl[3 * 256 * 128];        // B lo planes (fp16 residual)
__device__ __half g_yn[N_PAD * 128];          // neighbor-transform out (fp16)
__device__ __half g_ys[N_PAD * 128];          // self-transform out (fp16; also reused
                                              // as fp32 scratch for hs4/hn4)
__device__ __half g_h3[N_NODES * 104];        // layer-3 activation (fp16, pitch 104)
__device__ float g_invdeg[N_NODES];
__device__ int   g_rowcnt[N_NODES];
__device__ int   g_rowptr[N_NODES];
__device__ int   g_cursor[N_NODES];
__device__ int   g_csr[N_EDGES];
__device__ int   g_bsum[128];
__device__ float g_pool[N_GRAPHS * 5];
__device__ int   g_gcnt[N_GRAPHS];

// ---------------- PTX helpers ----------------
__device__ __forceinline__ uint32_t smem_u32(const void* p) {
    uint32_t a;
    asm("{ .reg .u64 t; cvta.to.shared.u64 t, %1; cvt.u32.u64 %0, t; }" : "=r"(a) : "l"(p));
    return a;
}
__device__ __forceinline__ void ldsm4(uint32_t* r, uint32_t addr) {
    asm volatile("ldmatrix.sync.aligned.m8n8.x4.shared.b16 {%0,%1,%2,%3}, [%4];"
                 : "=r"(r[0]), "=r"(r[1]), "=r"(r[2]), "=r"(r[3]) : "r"(addr));
}
__device__ __forceinline__ void mma16816h(float* c, const uint32_t* a,
                                          uint32_t b0, uint32_t b1) {
    asm volatile(
        "mma.sync.aligned.m16n8k16.row.col.f32.f16.f16.f32 "
        "{%0,%1,%2,%3}, {%4,%5,%6,%7}, {%8,%9}, {%0,%1,%2,%3};"
        : "+f"(c[0]), "+f"(c[1]), "+f"(c[2]), "+f"(c[3])
        : "r"(a[0]), "r"(a[1]), "r"(a[2]), "r"(a[3]), "r"(b0), "r"(b1));
}
__device__ __forceinline__ void cpa16(uint32_t d, const void* g) {
    asm volatile("cp.async.cg.shared.global [%0], [%1], 16;" :: "r"(d), "l"(g));
}
__device__ __forceinline__ void cp_commit() {
    asm volatile("cp.async.commit_group;" ::: "memory");
}
template<int N> __device__ __forceinline__ void cp_wait() {
    asm volatile("cp.async.wait_group %0;" :: "n"(N) : "memory");
}

// ---------------- fused init: zero + conv_in + 3x wconv ----------------
#define NCONV  (N_PAD * 128 / 256)         // 50048
#define NWC    384                         // 98304 / 256
#define NZERO  ((N_NODES + 255) / 256)     // 391

__global__ void k_init(const float* __restrict__ x,
                       const float* __restrict__ wn1, const float* __restrict__ ws1,
                       const float* __restrict__ wn2, const float* __restrict__ ws2,
                       const float* __restrict__ wn3, const float* __restrict__ ws3)
{
    int b = blockIdx.x;
    int tid = threadIdx.x;
    if (b < NCONV) {
        int idx = b * 256 + tid;
        int n = idx >> 7;
        float v = (n < N_NODES) ? x[idx] : 0.f;
        g_a[idx] = __float2half(v);
    } else if (b < NCONV + NWC) {
        int idx = (b - NCONV) * 256 + tid;      // 0 .. 98303
        int l = idx >> 15;                      // layer 0..2
        int li = idx & 32767;
        int n = li >> 7, k = li & 127;
        const float* Wn = (l == 0) ? wn1 : (l == 1) ? wn2 : wn3;
        const float* Ws = (l == 0) ? ws1 : (l == 1) ? ws2 : ws3;
        int K    = (l == 2) ? 118 : 128;
        int dout = (l == 0) ? 128 : (l == 1) ? 118 : 103;
        float v = 0.f;
        if (k < K) {
            if (n < 128) { if (n < dout) v = Wn[k * dout + n]; }
            else { int s = n - 128; if (s < dout) v = Ws[k * dout + s]; }
        }
        __half h = __float2half(v);
        __half lo = __float2half(v - __half2float(h));
        g_bh[idx] = h;
        g_bl[idx] = lo;
    } else {
        int i = (b - NCONV - NWC) * 256 + tid;
        if (i < N_NODES) g_rowcnt[i] = 0;
        if (i < N_GRAPHS * 5) g_pool[i] = 0.f;
        if (i < N_GRAPHS) g_gcnt[i] = 0;
    }
}

// ---------------- CSR build ----------------
__global__ void k_count(const int* __restrict__ dst) {
    int e = blockIdx.x * blockDim.x + threadIdx.x;
    if (e < N_EDGES) atomicAdd(&g_rowcnt[dst[e]], 1);
}

__global__ void k_scan1() {
    __shared__ int s[SCAN_B];
    int tid = threadIdx.x;
    int gid = blockIdx.x * SCAN_B + tid;
    int v = (gid < N_NODES) ? g_rowcnt[gid] : 0;
    s[tid] = v;
    __syncthreads();
    for (int off = 1; off < SCAN_B; off <<= 1) {
        int t = (tid >= off) ? s[tid - off] : 0;
        __syncthreads();
        s[tid] += t;
        __syncthreads();
    }
    if (gid < N_NODES) g_rowptr[gid] = s[tid] - v;
    if (tid == SCAN_B - 1) g_bsum[blockIdx.x] = s[tid];
}

// scan3: each block redundantly scans the 98 block sums, then finalizes its slice
__global__ void k_scan3() {
    __shared__ int s[128];
    int tid = threadIdx.x;
    if (tid < 128) s[tid] = (tid < NB_SCAN) ? g_bsum[tid] : 0;
    __syncthreads();
    if (tid < 128) {
        for (int off = 1; off < 128; off <<= 1) {
            int x = (tid >= off) ? s[tid - off] : 0;
            __syncthreads();
            s[tid] += x;
            __syncthreads();
        }
    } else {
        for (int off = 1; off < 128; off <<= 1) { __syncthreads(); __syncthreads(); }
    }
    int boff = (blockIdx.x > 0) ? s[blockIdx.x - 1] : 0;   // exclusive offset
    int gid = blockIdx.x * SCAN_B + tid;
    if (gid < N_NODES) {
        int rp = g_rowptr[gid] + boff;
        g_rowptr[gid] = rp;
        g_cursor[gid] = rp;
        int c = g_rowcnt[gid];
        g_invdeg[gid] = 1.0f / (float)(c > 0 ? c : 1);
    }
}

__global__ void k_fill(const int* __restrict__ src, const int* __restrict__ dst) {
    int e = blockIdx.x * blockDim.x + threadIdx.x;
    if (e < N_EDGES) {
        int pos = atomicAdd(&g_cursor[dst[e]], 1);
        g_csr[pos] = src[e];
    }
}

// ---------------- pipelined HMMA GEMM (fp16 2-product, R8 config) ----------------
// Per CTA: 128(m) x 128(n), 256 threads, 8 warps of 64x32 tiles, 2 CTAs/SM.
// K=128 in 4 chunks of 32, 2-stage cp.async.
// blockIdx.y = 0: B rows [0,128) (Wn) -> Yn;  = 1: B rows [128,256) -> Ys. Both fp16.
#define PITCH  80
#define PLANE  10240
#define STAGEB 30720                     // A + Bh + Bl
#define GEMM_SMEM 61440

__global__ void __launch_bounds__(256, 2)
k_gemm_pipe(const __half* __restrict__ a,
            const __half* __restrict__ bh, const __half* __restrict__ bl,
            __half* __restrict__ Yn, __half* __restrict__ Ys)
{
    extern __shared__ char smem[];
    const int tid = threadIdx.x;
    const int m0 = blockIdx.x * 128;
    const int n0 = blockIdx.y * 128;
    const uint32_t sb = smem_u32(smem);

    const int f_row = tid >> 2;          // 64 rows per pass
    const int f_kc  = tid & 3;
    #define FILL(st, ks) do {                                                  \
        uint32_t sbase = sb + (st) * STAGEB;                                   \
        _Pragma("unroll")                                                      \
        for (int i = 0; i < 2; ++i) {                                          \
            int row = f_row + i * 64;                                          \
            uint32_t doff = row * PITCH + f_kc * 16;                           \
            size_t ga = (size_t)(m0 + row) * 128 + (ks) * 32 + f_kc * 8;       \
            size_t gb = (size_t)(n0 + row) * 128 + (ks) * 32 + f_kc * 8;       \
            cpa16(sbase + doff,             a  + ga);                          \
            cpa16(sbase + PLANE + doff,     bh + gb);                          \
            cpa16(sbase + 2 * PLANE + doff, bl + gb);                          \
        }                                                                      \
    } while (0)

    FILL(0, 0); cp_commit();
    FILL(1, 1); cp_commit();

    const int wid = tid >> 5, lane = tid & 31;
    const int wm  = (wid & 1) * 64;
    const int wn2 = (wid >> 1) * 32;

    float acc[4][4][4];
    #pragma unroll
    for (int mf = 0; mf < 4; ++mf)
        #pragma unroll
        for (int nf = 0; nf < 4; ++nf)
            #pragma unroll
            for (int q = 0; q < 4; ++q) acc[mf][nf][q] = 0.f;

    const uint32_t aL = (uint32_t)(lane & 15) * PITCH + (lane >> 4) * 16;
    const uint32_t bL = (uint32_t)((lane & 7) + ((lane >> 4) << 3)) * PITCH
                        + ((lane >> 3) & 1) * 16;

    #pragma unroll
    for (int ks = 0; ks < 4; ++ks) {
        cp_wait<1>();
        __syncthreads();
        const uint32_t st = sb + (ks & 1) * STAGEB;
        #pragma unroll
        for (int kk = 0; kk < 2; ++kk) {
            const uint32_t kb = kk * 32;
            uint32_t A4[4][4], Bh4[2][4], Bl4[2][4];
            #pragma unroll
            for (int mf = 0; mf < 4; ++mf)
                ldsm4(A4[mf], st + (uint32_t)(wm + mf * 16) * PITCH + aL + kb);
            #pragma unroll
            for (int nq = 0; nq < 2; ++nq) {
                uint32_t bbase = st + PLANE + (uint32_t)(wn2 + nq * 16) * PITCH + bL + kb;
                ldsm4(Bh4[nq], bbase);
                ldsm4(Bl4[nq], bbase + PLANE);
            }
            #pragma unroll
            for (int nq = 0; nq < 2; ++nq)
                #pragma unroll
                for (int mf = 0; mf < 4; ++mf) {
                    float* c0 = acc[mf][2 * nq];
                    float* c1 = acc[mf][2 * nq + 1];
                    mma16816h(c0, A4[mf], Bh4[nq][0], Bh4[nq][1]);
                    mma16816h(c0, A4[mf], Bl4[nq][0], Bl4[nq][1]);
                    mma16816h(c1, A4[mf], Bh4[nq][2], Bh4[nq][3]);
                    mma16816h(c1, A4[mf], Bl4[nq][2], Bl4[nq][3]);
                }
        }
        __syncthreads();
        if (ks + 2 < 4) FILL(ks & 1, ks + 2);
        cp_commit();
    }

    // ---- epilogue: both halves write fp16, pitch 128 ----
    __half* dst = (blockIdx.y == 0) ? Yn : Ys;
    const int gid = lane >> 2, tig = lane & 3;
    #pragma unroll
    for (int mf = 0; mf < 4; ++mf) {
        int r = m0 + wm + mf * 16 + gid;
        #pragma unroll
        for (int nf = 0; nf < 4; ++nf) {
            int col = wn2 + nf * 8 + tig * 2;
            *(__half2*)&dst[(size_t)r * 128 + col] =
                __floats2half2_rn(acc[mf][nf][0], acc[mf][nf][1]);
            *(__half2*)&dst[(size_t)(r + 8) * 128 + col] =
                __floats2half2_rn(acc[mf][nf][2], acc[mf][nf][3]);
        }
    }
}

// ---------------- fused aggregation + epilogue ----------------
// Half-warp (16 lanes) per node, uint4 per lane, 4 edges in flight.
// h = relu?( Ys[n,c] + invdeg[n]*sum Yn[s,c] + b[c] );  OUTH=1: fp16 pitch 128 (zero-pad);
// OUTH=0: fp16 pitch 104 (lanes 0..12).
template<int DOUT, int RELU, int OUTH>
__global__ void k_agg(const __half* __restrict__ Yn, const __half* __restrict__ Ys,
                      const float* __restrict__ bias,
                      __half* __restrict__ oh, __half* __restrict__ of)
{
    int node = (int)((blockIdx.x * blockDim.x + threadIdx.x) >> 4);
    int l = threadIdx.x & 15;
    if (node >= N_NODES) return;
    int beg = g_rowptr[node];
    int cnt = g_rowcnt[node];
    const int c = l * 8;

    float s[8];
    #pragma unroll
    for (int t = 0; t < 8; ++t) s[t] = 0.f;

    int j = 0;
    for (; j + 4 <= cnt; j += 4) {
        int i0 = g_csr[beg + j];
        int i1 = g_csr[beg + j + 1];
        int i2 = g_csr[beg + j + 2];
        int i3 = g_csr[beg + j + 3];
        uint4 u0 = *(const uint4*)(Yn + (size_t)i0 * 128 + c);
        uint4 u1 = *(const uint4*)(Yn + (size_t)i1 * 128 + c);
        uint4 u2 = *(const uint4*)(Yn + (size_t)i2 * 128 + c);
        uint4 u3 = *(const uint4*)(Yn + (size_t)i3 * 128 + c);
        const __half2* h0 = (const __half2*)&u0;
        const __half2* h1 = (const __half2*)&u1;
        const __half2* h2 = (const __half2*)&u2;
        const __half2* h3 = (const __half2*)&u3;
        #pragma unroll
        for (int q = 0; q < 4; ++q) {
            float2 f0 = __half22float2(h0[q]);
            float2 f1 = __half22float2(h1[q]);
            float2 f2 = __half22float2(h2[q]);
            float2 f3 = __half22float2(h3[q]);
            s[2 * q]     += (f0.x + f1.x) + (f2.x + f3.x);
            s[2 * q + 1] += (f0.y + f1.y) + (f2.y + f3.y);
        }
    }
    for (; j < cnt; ++j) {
        int i0 = g_csr[beg + j];
        uint4 u0 = *(const uint4*)(Yn + (size_t)i0 * 128 + c);
        const __half2* h0 = (const __half2*)&u0;
        #pragma unroll
        for (int q = 0; q < 4; ++q) {
            float2 f0 = __half22float2(h0[q]);
            s[2 * q]     += f0.x;
            s[2 * q + 1] += f0.y;
        }
    }

    float inv = g_invdeg[node];
    uint4 su = *(const uint4*)(Ys + (size_t)node * 128 + c);
    const __half2* sh = (const __half2*)&su;
    float selfv[8];
    #pragma unroll
    for (int q = 0; q < 4; ++q) {
        float2 f = __half22float2(sh[q]);
        selfv[2 * q] = f.x;
        selfv[2 * q + 1] = f.y;
    }
    float v[8];
    #pragma unroll
    for (int t = 0; t < 8; ++t) {
        int cc = c + t;
        if (cc < DOUT) {
            float x = selfv[t] + s[t] * inv + bias[cc];
            v[t] = RELU ? fmaxf(x, 0.f) : x;
        } else {
            v[t] = 0.f;
        }
    }

    union { __half2 h2[4]; uint4 u; } uo;
    #pragma unroll
    for (int q = 0; q < 4; ++q)
        uo.h2[q] = __floats2half2_rn(v[2 * q], v[2 * q + 1]);

    if (OUTH) {
        *(uint4*)(oh + (size_t)node * 128 + c) = uo.u;
    } else {
        if (c < 104)        // lanes 0..12 cover 104 halves (pitch 104, 16B aligned)
            *(uint4*)(of + (size_t)node * 104 + c) = uo.u;
    }
}

// ---------------- layer 4: tiny GEMM (N=10), fp16 input ----------------
__global__ void k_gemm4(const __half* __restrict__ h3,
                        const float* __restrict__ ws4, const float* __restrict__ wn4,
                        float* __restrict__ hs4, float* __restrict__ hn4)
{
    __shared__ float sW[1040];
    int tid = threadIdx.x;
    for (int idx = tid; idx < 1040; idx += 256) {
        int k = idx / 10, cc = idx % 10;
        sW[idx] = (k < 103) ? ((cc < 5) ? ws4[k * 5 + cc] : wn4[k * 5 + (cc - 5)]) : 0.f;
    }
    __syncthreads();
    int node = blockIdx.x * 16 + (tid >> 4);
    int cc = tid & 15;
    if (node >= N_NODES || cc >= 10) return;
    const uint4* row = (const uint4*)(h3 + (size_t)node * 104);
    float acc = 0.f;
    #pragma unroll 13
    for (int kc = 0; kc < 13; ++kc) {
        uint4 u = __ldg(row + kc);
        const __half2* hp = (const __half2*)&u;
        int kb = kc * 80;               // 8k * 10
        #pragma unroll
        for (int q = 0; q < 4; ++q) {
            float2 f = __half22float2(hp[q]);
            acc += f.x * sW[kb + q * 20 + cc] + f.y * sW[kb + q * 20 + 10 + cc];
        }
    }
    if (cc < 5) hs4[node * 8 + cc] = acc;
    else        hn4[node * 8 + (cc - 5)] = acc;
}

// layer 4 aggregation fused with graph pooling
__global__ void k_agg4pool(const float* __restrict__ hn4, const float* __restrict__ hs4,
                           const float* __restrict__ b4, const int* __restrict__ gids)
{
    int n = blockIdx.x * blockDim.x + threadIdx.x;
    if (n >= N_NODES) return;
    int beg = g_rowptr[n], cnt = g_rowcnt[n];
    float a0 = 0.f, a1 = 0.f, a2 = 0.f, a3 = 0.f, a4 = 0.f;
    for (int j = 0; j < cnt; ++j) {
        const float* r = hn4 + (size_t)g_csr[beg + j] * 8;
        a0 += __ldg(r + 0); a1 += __ldg(r + 1); a2 += __ldg(r + 2);
        a3 += __ldg(r + 3); a4 += __ldg(r + 4);
    }
    float inv = g_invdeg[n];
    int g = gids[n];
    atomicAdd(&g_gcnt[g], 1);
    atomicAdd(&g_pool[g * 5 + 0], hs4[n * 8 + 0] + inv * a0 + b4[0]);
    atomicAdd(&g_pool[g * 5 + 1], hs4[n * 8 + 1] + inv * a1 + b4[1]);
    atomicAdd(&g_pool[g * 5 + 2], hs4[n * 8 + 2] + inv * a2 + b4[2]);
    atomicAdd(&g_pool[g * 5 + 3], hs4[n * 8 + 3] + inv * a3 + b4[3]);
    atomicAdd(&g_pool[g * 5 + 4], hs4[n * 8 + 4] + inv * a4 + b4[4]);
}

__global__ void k_final(float* __restrict__ out) {
    int i = blockIdx.x * blockDim.x + threadIdx.x;
    if (i < N_GRAPHS * 5) {
        int g = i / 5;
        int c = g_gcnt[g];
        out[i] = g_pool[i] / (float)(c > 0 ? c : 1);
    }
}

// ---------------- launch ----------------
extern "C" void kernel_launch(void* const* d_in, const int* in_sizes, int n_in,
                              void* d_out, int out_size)
{
    const float* in_feat = (const float*)d_in[0];
    const int*   src     = (const int*)d_in[1];
    const int*   dst     = (const int*)d_in[2];
    const int*   gids    = (const int*)d_in[3];
    const float* ws[4] = { (const float*)d_in[4],  (const float*)d_in[7],
                           (const float*)d_in[10], (const float*)d_in[13] };
    const float* wn[4] = { (const float*)d_in[5],  (const float*)d_in[8],
                           (const float*)d_in[11], (const float*)d_in[14] };
    const float* bs[4] = { (const float*)d_in[6],  (const float*)d_in[9],
                           (const float*)d_in[12], (const float*)d_in[15] };

    __half *a, *bh, *bl, *yn, *ys, *h3;
    cudaGetSymbolAddress((void**)&a,  g_a);
    cudaGetSymbolAddress((void**)&bh, g_bh);
    cudaGetSymbolAddress((void**)&bl, g_bl);
    cudaGetSymbolAddress((void**)&yn, g_yn);
    cudaGetSymbolAddress((void**)&ys, g_ys);
    cudaGetSymbolAddress((void**)&h3, g_h3);
    float* hs4 = (float*)ys;                 // g_ys raw memory free after agg3
    float* hn4 = (float*)ys + 800000;

    cudaFuncSetAttribute(k_gemm_pipe, cudaFuncAttributeMaxDynamicSharedMemorySize, GEMM_SMEM);

    // side stream + fork/join events, created once outside any capture
    static cudaStream_t s1 = nullptr;
    static cudaEvent_t  e0 = nullptr, e1 = nullptr;
    if (s1 == nullptr) {
        cudaStreamCreateWithFlags(&s1, cudaStreamNonBlocking);
        cudaEventCreateWithFlags(&e0, cudaEventDisableTiming);
        cudaEventCreateWithFlags(&e1, cudaEventDisableTiming);
    }

    const int TB = 256;
    const dim3 gemmGrid(N_PAD / 128, 2);                  // 782 x 2
    const int aggBlocks = (N_NODES * 16 + TB - 1) / TB;   // half-warp per node

    // idx0: init (zero + conv_in + wconv x3) on main stream
    k_init<<<NCONV + NWC + NZERO, TB>>>(in_feat, wn[0], ws[0], wn[1], ws[1],
                                        wn[2], ws[2]);
    cudaEventRecord(e0, 0);
    cudaStreamWaitEvent(s1, e0, 0);

    // CSR build on side stream
    k_count<<<(N_EDGES + TB - 1) / TB, TB, 0, s1>>>(dst);                    // idx1
    k_scan1<<<NB_SCAN, SCAN_B, 0, s1>>>();                                   // idx2
    // idx3 (profiled): layer-1 GEMM on main stream
    k_gemm_pipe<<<gemmGrid, TB, GEMM_SMEM>>>(a, bh, bl, yn, ys);
    k_scan3<<<NB_SCAN, SCAN_B, 0, s1>>>();                                   // idx4
    k_fill<<<(N_EDGES + TB - 1) / TB, TB, 0, s1>>>(src, dst);                // idx5
    cudaEventRecord(e1, s1);
    cudaStreamWaitEvent(0, e1, 0);

    // layer 1 epilogue -> fp16 activations for layer 2
    k_agg<128, 1, 1><<<aggBlocks, TB>>>(yn, ys, bs[0], a, nullptr);          // idx6
    // layer 2
    k_gemm_pipe<<<gemmGrid, TB, GEMM_SMEM>>>(a, bh + 32768, bl + 32768, yn, ys); // idx7
    k_agg<118, 1, 1><<<aggBlocks, TB>>>(yn, ys, bs[1], a, nullptr);          // idx8
    // layer 3
    k_gemm_pipe<<<gemmGrid, TB, GEMM_SMEM>>>(a, bh + 65536, bl + 65536, yn, ys); // idx9
    k_agg<103, 1, 0><<<aggBlocks, TB>>>(yn, ys, bs[2], nullptr, h3);         // idx10
    // layer 4 (SIMT, tiny) + pooling
    k_gemm4<<<(N_NODES + 15) / 16, TB>>>(h3, ws[3], wn[3], hs4, hn4);        // idx11
    k_agg4pool<<<(N_NODES + TB - 1) / TB, TB>>>(hn4, hs4, bs[3], gids);      // idx12
    k_final<<<1, 512>>>((float*)d_out);                                      // idx13
}

// round 15
// speedup vs baseline: 1.2317x; 1.0458x over previous
#include <cuda_runtime.h>
#include <cuda_bf16.h>
#include <cuda_fp16.h>
#include <cooperative_groups.h>
#include <cstdint>

namespace cg = cooperative_groups;

#define N_NODES  100000
#define N_PAD    100096          // 782 * 128
#define N_EDGES  1600000
#define N_GRAPHS 100
#define NB_SCAN  98              // 98 * 1024 >= N_NODES

// ---------------- scratch (static __device__ allocations only) ----------------
__device__ __half g_a [N_PAD * 128];          // activations, fp16, pitch 128
__device__ __half g_bh[3 * 256 * 128];        // B hi planes, layer l at offset l*32768
__device__ __half g_bl[3 * 256 * 128];        // B lo planes (fp16 residual)
__device__ __half g_yn[N_PAD * 128];          // neighbor-transform out (fp16)
__device__ __half g_ys[N_PAD * 128];          // self-transform out (fp16; raw space
                                              // reused as fp32 hs4/hn4 after agg3)
__device__ __half g_h3[N_NODES * 104];        // layer-3 activation (fp16, pitch 104)
__device__ float g_invdeg[N_NODES];
__device__ int   g_rowcnt[N_NODES];
__device__ int   g_rowptr[N_NODES];
__device__ int   g_cursor[N_NODES];
__device__ int   g_csr[N_EDGES];
__device__ int   g_bsum[128];
__device__ int   g_boff[128];
__device__ float g_pool[N_GRAPHS * 5];
__device__ int   g_gcnt[N_GRAPHS];

// ---------------- PTX helpers ----------------
__device__ __forceinline__ uint32_t smem_u32(const void* p) {
    uint32_t a;
    asm("{ .reg .u64 t; cvta.to.shared.u64 t, %1; cvt.u32.u64 %0, t; }" : "=r"(a) : "l"(p));
    return a;
}
__device__ __forceinline__ void ldsm4(uint32_t* r, uint32_t addr) {
    asm volatile("ldmatrix.sync.aligned.m8n8.x4.shared.b16 {%0,%1,%2,%3}, [%4];"
                 : "=r"(r[0]), "=r"(r[1]), "=r"(r[2]), "=r"(r[3]) : "r"(addr));
}
__device__ __forceinline__ void mma16816h(float* c, const uint32_t* a,
                                          uint32_t b0, uint32_t b1) {
    asm volatile(
        "mma.sync.aligned.m16n8k16.row.col.f32.f16.f16.f32 "
        "{%0,%1,%2,%3}, {%4,%5,%6,%7}, {%8,%9}, {%0,%1,%2,%3};"
        : "+f"(c[0]), "+f"(c[1]), "+f"(c[2]), "+f"(c[3])
        : "r"(a[0]), "r"(a[1]), "r"(a[2]), "r"(a[3]), "r"(b0), "r"(b1));
}
__device__ __forceinline__ void cpa16(uint32_t d, const void* g) {
    asm volatile("cp.async.cg.shared.global [%0], [%1], 16;" :: "r"(d), "l"(g));
}
__device__ __forceinline__ void cp_commit() {
    asm volatile("cp.async.commit_group;" ::: "memory");
}
template<int N> __device__ __forceinline__ void cp_wait() {
    asm volatile("cp.async.wait_group %0;" :: "n"(N) : "memory");
}

// ---------------- fused init: zero + conv_in + 3x wconv ----------------
#define NCONV  (N_PAD * 128 / 256)         // 50048
#define NWC    384                         // 98304 / 256
#define NZERO  ((N_NODES + 255) / 256)     // 391

__global__ void k_init(const float* __restrict__ x,
                       const float* __restrict__ wn1, const float* __restrict__ ws1,
                       const float* __restrict__ wn2, const float* __restrict__ ws2,
                       const float* __restrict__ wn3, const float* __restrict__ ws3)
{
    int b = blockIdx.x;
    int tid = threadIdx.x;
    if (b < NCONV) {
        int idx = b * 256 + tid;
        int n = idx >> 7;
        float v = (n < N_NODES) ? x[idx] : 0.f;
        g_a[idx] = __float2half(v);
    } else if (b < NCONV + NWC) {
        int idx = (b - NCONV) * 256 + tid;      // 0 .. 98303
        int l = idx >> 15;                      // layer 0..2
        int li = idx & 32767;
        int n = li >> 7, k = li & 127;
        const float* Wn = (l == 0) ? wn1 : (l == 1) ? wn2 : wn3;
        const float* Ws = (l == 0) ? ws1 : (l == 1) ? ws2 : ws3;
        int K    = (l == 2) ? 118 : 128;
        int dout = (l == 0) ? 128 : (l == 1) ? 118 : 103;
        float v = 0.f;
        if (k < K) {
            if (n < 128) { if (n < dout) v = Wn[k * dout + n]; }
            else { int s = n - 128; if (s < dout) v = Ws[k * dout + s]; }
        }
        __half h = __float2half(v);
        __half lo = __float2half(v - __half2float(h));
        g_bh[idx] = h;
        g_bl[idx] = lo;
    } else {
        int i = (b - NCONV - NWC) * 256 + tid;
        if (i < N_NODES) g_rowcnt[i] = 0;
        if (i < N_GRAPHS * 5) g_pool[i] = 0.f;
        if (i < N_GRAPHS) g_gcnt[i] = 0;
    }
}

// ---------------- cooperative CSR build: count + scan + finalize + fill ----------------
// 148 blocks x 1024 threads (one CTA/SM, co-resident), 4 grid syncs.
__global__ void k_csr(const int* __restrict__ src, const int* __restrict__ dst)
{
    cg::grid_group grid = cg::this_grid();
    const int tid = threadIdx.x;
    const int b = blockIdx.x;
    const int gthread = b * 1024 + tid;
    const int nthreads = gridDim.x * 1024;
    __shared__ int s[1024];

    // phase 1: count in-degrees
    for (int e = gthread; e < N_EDGES; e += nthreads)
        atomicAdd(&g_rowcnt[dst[e]], 1);
    grid.sync();

    // phase 2: per-block exclusive scan of a 1024-chunk (blocks 0..97)
    int v2 = 0;
    if (b < NB_SCAN) {
        int gid = b * 1024 + tid;
        v2 = (gid < N_NODES) ? g_rowcnt[gid] : 0;
        s[tid] = v2;
        __syncthreads();
        for (int off = 1; off < 1024; off <<= 1) {
            int t = (tid >= off) ? s[tid - off] : 0;
            __syncthreads();
            s[tid] += t;
            __syncthreads();
        }
        if (gid < N_NODES) g_rowptr[gid] = s[tid] - v2;   // exclusive within block
        if (tid == 1023) g_bsum[b] = s[tid];
    }
    grid.sync();

    // phase 3: block 0 scans the 98 block sums -> exclusive offsets
    if (b == 0) {
        int v0 = 0;
        if (tid < 128) {
            v0 = (tid < NB_SCAN) ? g_bsum[tid] : 0;
            s[tid] = v0;
        }
        __syncthreads();
        for (int off = 1; off < 128; off <<= 1) {
            int x = (tid >= off && tid < 128) ? s[tid - off] : 0;
            __syncthreads();
            if (tid < 128) s[tid] += x;
            __syncthreads();
        }
        if (tid < NB_SCAN) g_boff[tid] = s[tid] - v0;     // exclusive
    }
    grid.sync();

    // phase 4: finalize rowptr / cursor / invdeg
    if (b < NB_SCAN) {
        int gid = b * 1024 + tid;
        if (gid < N_NODES) {
            int rp = g_rowptr[gid] + g_boff[b];
            g_rowptr[gid] = rp;
            g_cursor[gid] = rp;
            int c = g_rowcnt[gid];
            g_invdeg[gid] = 1.0f / (float)(c > 0 ? c : 1);
        }
    }
    grid.sync();

    // phase 5: fill CSR
    for (int e = gthread; e < N_EDGES; e += nthreads) {
        int pos = atomicAdd(&g_cursor[dst[e]], 1);
        g_csr[pos] = src[e];
    }
}

// ---------------- pipelined HMMA GEMM (fp16 2-product, R8 config) ----------------
#define PITCH  80
#define PLANE  10240
#define STAGEB 30720                     // A + Bh + Bl
#define GEMM_SMEM 61440

__global__ void __launch_bounds__(256, 2)
k_gemm_pipe(const __half* __restrict__ a,
            const __half* __restrict__ bh, const __half* __restrict__ bl,
            __half* __restrict__ Yn, __half* __restrict__ Ys)
{
    extern __shared__ char smem[];
    const int tid = threadIdx.x;
    const int m0 = blockIdx.x * 128;
    const int n0 = blockIdx.y * 128;
    const uint32_t sb = smem_u32(smem);

    const int f_row = tid >> 2;          // 64 rows per pass
    const int f_kc  = tid & 3;
    #define FILL(st, ks) do {                                                  \
        uint32_t sbase = sb + (st) * STAGEB;                                   \
        _Pragma("unroll")                                                      \
        for (int i = 0; i < 2; ++i) {                                          \
            int row = f_row + i * 64;                                          \
            uint32_t doff = row * PITCH + f_kc * 16;                           \
            size_t ga = (size_t)(m0 + row) * 128 + (ks) * 32 + f_kc * 8;       \
            size_t gb = (size_t)(n0 + row) * 128 + (ks) * 32 + f_kc * 8;       \
            cpa16(sbase + doff,             a  + ga);                          \
            cpa16(sbase + PLANE + doff,     bh + gb);                          \
            cpa16(sbase + 2 * PLANE + doff, bl + gb);                          \
        }                                                                      \
    } while (0)

    FILL(0, 0); cp_commit();
    FILL(1, 1); cp_commit();

    const int wid = tid >> 5, lane = tid & 31;
    const int wm  = (wid & 1) * 64;
    const int wn2 = (wid >> 1) * 32;

    float acc[4][4][4];
    #pragma unroll
    for (int mf = 0; mf < 4; ++mf)
        #pragma unroll
        for (int nf = 0; nf < 4; ++nf)
            #pragma unroll
            for (int q = 0; q < 4; ++q) acc[mf][nf][q] = 0.f;

    const uint32_t aL = (uint32_t)(lane & 15) * PITCH + (lane >> 4) * 16;
    const uint32_t bL = (uint32_t)((lane & 7) + ((lane >> 4) << 3)) * PITCH
                        + ((lane >> 3) & 1) * 16;

    #pragma unroll
    for (int ks = 0; ks < 4; ++ks) {
        cp_wait<1>();
        __syncthreads();
        const uint32_t st = sb + (ks & 1) * STAGEB;
        #pragma unroll
        for (int kk = 0; kk < 2; ++kk) {
            const uint32_t kb = kk * 32;
            uint32_t A4[4][4], Bh4[2][4], Bl4[2][4];
            #pragma unroll
            for (int mf = 0; mf < 4; ++mf)
                ldsm4(A4[mf], st + (uint32_t)(wm + mf * 16) * PITCH + aL + kb);
            #pragma unroll
            for (int nq = 0; nq < 2; ++nq) {
                uint32_t bbase = st + PLANE + (uint32_t)(wn2 + nq * 16) * PITCH + bL + kb;
                ldsm4(Bh4[nq], bbase);
                ldsm4(Bl4[nq], bbase + PLANE);
            }
            #pragma unroll
            for (int nq = 0; nq < 2; ++nq)
                #pragma unroll
                for (int mf = 0; mf < 4; ++mf) {
                    float* c0 = acc[mf][2 * nq];
                    float* c1 = acc[mf][2 * nq + 1];
                    mma16816h(c0, A4[mf], Bh4[nq][0], Bh4[nq][1]);
                    mma16816h(c0, A4[mf], Bl4[nq][0], Bl4[nq][1]);
                    mma16816h(c1, A4[mf], Bh4[nq][2], Bh4[nq][3]);
                    mma16816h(c1, A4[mf], Bl4[nq][2], Bl4[nq][3]);
                }
        }
        __syncthreads();
        if (ks + 2 < 4) FILL(ks & 1, ks + 2);
        cp_commit();
    }

    // ---- epilogue: both halves write fp16, pitch 128 ----
    __half* dst = (blockIdx.y == 0) ? Yn : Ys;
    const int gid = lane >> 2, tig = lane & 3;
    #pragma unroll
    for (int mf = 0; mf < 4; ++mf) {
        int r = m0 + wm + mf * 16 + gid;
        #pragma unroll
        for (int nf = 0; nf < 4; ++nf) {
            int col = wn2 + nf * 8 + tig * 2;
            *(__half2*)&dst[(size_t)r * 128 + col] =
                __floats2half2_rn(acc[mf][nf][0], acc[mf][nf][1]);
            *(__half2*)&dst[(size_t)(r + 8) * 128 + col] =
                __floats2half2_rn(acc[mf][nf][2], acc[mf][nf][3]);
        }
    }
}

// ---------------- fused aggregation + epilogue ----------------
// Half-warp (16 lanes) per node, uint4 per lane, 4 edges in flight.
template<int DOUT, int RELU, int OUTH>
__global__ void k_agg(const __half* __restrict__ Yn, const __half* __restrict__ Ys,
                      const float* __restrict__ bias,
                      __half* __restrict__ oh, __half* __restrict__ of)
{
    int node = (int)((blockIdx.x * blockDim.x + threadIdx.x) >> 4);
    int l = threadIdx.x & 15;
    if (node >= N_NODES) return;
    int beg = g_rowptr[node];
    int cnt = g_rowcnt[node];
    const int c = l * 8;

    float s[8];
    #pragma unroll
    for (int t = 0; t < 8; ++t) s[t] = 0.f;

    int j = 0;
    for (; j + 4 <= cnt; j += 4) {
        int i0 = g_csr[beg + j];
        int i1 = g_csr[beg + j + 1];
        int i2 = g_csr[beg + j + 2];
        int i3 = g_csr[beg + j + 3];
        uint4 u0 = *(const uint4*)(Yn + (size_t)i0 * 128 + c);
        uint4 u1 = *(const uint4*)(Yn + (size_t)i1 * 128 + c);
        uint4 u2 = *(const uint4*)(Yn + (size_t)i2 * 128 + c);
        uint4 u3 = *(const uint4*)(Yn + (size_t)i3 * 128 + c);
        const __half2* h0 = (const __half2*)&u0;
        const __half2* h1 = (const __half2*)&u1;
        const __half2* h2 = (const __half2*)&u2;
        const __half2* h3 = (const __half2*)&u3;
        #pragma unroll
        for (int q = 0; q < 4; ++q) {
            float2 f0 = __half22float2(h0[q]);
            float2 f1 = __half22float2(h1[q]);
            float2 f2 = __half22float2(h2[q]);
            float2 f3 = __half22float2(h3[q]);
            s[2 * q]     += (f0.x + f1.x) + (f2.x + f3.x);
            s[2 * q + 1] += (f0.y + f1.y) + (f2.y + f3.y);
        }
    }
    for (; j < cnt; ++j) {
        int i0 = g_csr[beg + j];
        uint4 u0 = *(const uint4*)(Yn + (size_t)i0 * 128 + c);
        const __half2* h0 = (const __half2*)&u0;
        #pragma unroll
        for (int q = 0; q < 4; ++q) {
            float2 f0 = __half22float2(h0[q]);
            s[2 * q]     += f0.x;
            s[2 * q + 1] += f0.y;
        }
    }

    float inv = g_invdeg[node];
    uint4 su = *(const uint4*)(Ys + (size_t)node * 128 + c);
    const __half2* sh = (const __half2*)&su;
    float selfv[8];
    #pragma unroll
    for (int q = 0; q < 4; ++q) {
        float2 f = __half22float2(sh[q]);
        selfv[2 * q] = f.x;
        selfv[2 * q + 1] = f.y;
    }
    float v[8];
    #pragma unroll
    for (int t = 0; t < 8; ++t) {
        int cc = c + t;
        if (cc < DOUT) {
            float x = selfv[t] + s[t] * inv + bias[cc];
            v[t] = RELU ? fmaxf(x, 0.f) : x;
        } else {
            v[t] = 0.f;
        }
    }

    union { __half2 h2[4]; uint4 u; } uo;
    #pragma unroll
    for (int q = 0; q < 4; ++q)
        uo.h2[q] = __floats2half2_rn(v[2 * q], v[2 * q + 1]);

    if (OUTH) {
        *(uint4*)(oh + (size_t)node * 128 + c) = uo.u;
    } else {
        if (c < 104)
            *(uint4*)(of + (size_t)node * 104 + c) = uo.u;
    }
}

// ---------------- layer 4: tiny GEMM (N=10), fp16 input ----------------
__global__ void k_gemm4(const __half* __restrict__ h3,
                        const float* __restrict__ ws4, const float* __restrict__ wn4,
                        float* __restrict__ hs4, float* __restrict__ hn4)
{
    __shared__ float sW[1040];
    int tid = threadIdx.x;
    for (int idx = tid; idx < 1040; idx += 256) {
        int k = idx / 10, cc = idx % 10;
        sW[idx] = (k < 103) ? ((cc < 5) ? ws4[k * 5 + cc] : wn4[k * 5 + (cc - 5)]) : 0.f;
    }
    __syncthreads();
    int node = blockIdx.x * 16 + (tid >> 4);
    int cc = tid & 15;
    if (node >= N_NODES || cc >= 10) return;
    const uint4* row = (const uint4*)(h3 + (size_t)node * 104);
    float acc = 0.f;
    #pragma unroll 13
    for (int kc = 0; kc < 13; ++kc) {
        uint4 u = __ldg(row + kc);
        const __half2* hp = (const __half2*)&u;
        int kb = kc * 80;               // 8k * 10
        #pragma unroll
        for (int q = 0; q < 4; ++q) {
            float2 f = __half22float2(hp[q]);
            acc += f.x * sW[kb + q * 20 + cc] + f.y * sW[kb + q * 20 + 10 + cc];
        }
    }
    if (cc < 5) hs4[node * 8 + cc] = acc;
    else        hn4[node * 8 + (cc - 5)] = acc;
}

// layer 4 aggregation fused with graph pooling
__global__ void k_agg4pool(const float* __restrict__ hn4, const float* __restrict__ hs4,
                           const float* __restrict__ b4, const int* __restrict__ gids)
{
    int n = blockIdx.x * blockDim.x + threadIdx.x;
    if (n >= N_NODES) return;
    int beg = g_rowptr[n], cnt = g_rowcnt[n];
    float a0 = 0.f, a1 = 0.f, a2 = 0.f, a3 = 0.f, a4 = 0.f;
    for (int j = 0; j < cnt; ++j) {
        const float* r = hn4 + (size_t)g_csr[beg + j] * 8;
        float4 p = __ldg((const float4*)r);
        float  q = __ldg(r + 4);
        a0 += p.x; a1 += p.y; a2 += p.z; a3 += p.w; a4 += q;
    }
    float inv = g_invdeg[n];
    int g = gids[n];
    atomicAdd(&g_gcnt[g], 1);
    atomicAdd(&g_pool[g * 5 + 0], hs4[n * 8 + 0] + inv * a0 + b4[0]);
    atomicAdd(&g_pool[g * 5 + 1], hs4[n * 8 + 1] + inv * a1 + b4[1]);
    atomicAdd(&g_pool[g * 5 + 2], hs4[n * 8 + 2] + inv * a2 + b4[2]);
    atomicAdd(&g_pool[g * 5 + 3], hs4[n * 8 + 3] + inv * a3 + b4[3]);
    atomicAdd(&g_pool[g * 5 + 4], hs4[n * 8 + 4] + inv * a4 + b4[4]);
}

__global__ void k_final(float* __restrict__ out) {
    int i = blockIdx.x * blockDim.x + threadIdx.x;
    if (i < N_GRAPHS * 5) {
        int g = i / 5;
        int c = g_gcnt[g];
        out[i] = g_pool[i] / (float)(c > 0 ? c : 1);
    }
}

// ---------------- launch ----------------
extern "C" void kernel_launch(void* const* d_in, const int* in_sizes, int n_in,
                              void* d_out, int out_size)
{
    const float* in_feat = (const float*)d_in[0];
    const int*   src     = (const int*)d_in[1];
    const int*   dst     = (const int*)d_in[2];
    const int*   gids    = (const int*)d_in[3];
    const float* ws[4] = { (const float*)d_in[4],  (const float*)d_in[7],
                           (const float*)d_in[10], (const float*)d_in[13] };
    const float* wn[4] = { (const float*)d_in[5],  (const float*)d_in[8],
                           (const float*)d_in[11], (const float*)d_in[14] };
    const float* bs[4] = { (const float*)d_in[6],  (const float*)d_in[9],
                           (const float*)d_in[12], (const float*)d_in[15] };

    __half *a, *bh, *bl, *yn, *ys, *h3;
    cudaGetSymbolAddress((void**)&a,  g_a);
    cudaGetSymbolAddress((void**)&bh, g_bh);
    cudaGetSymbolAddress((void**)&bl, g_bl);
    cudaGetSymbolAddress((void**)&yn, g_yn);
    cudaGetSymbolAddress((void**)&ys, g_ys);
    cudaGetSymbolAddress((void**)&h3, g_h3);
    float* hs4 = (float*)ys;                 // g_ys raw memory free after agg3
    float* hn4 = (float*)ys + 800000;

    cudaFuncSetAttribute(k_gemm_pipe, cudaFuncAttributeMaxDynamicSharedMemorySize, GEMM_SMEM);

    const int TB = 256;
    const dim3 gemmGrid(N_PAD / 128, 2);                  // 782 x 2
    const int aggBlocks = (N_NODES * 16 + TB - 1) / TB;   // half-warp per node

    // idx0: init (zero + conv_in + wconv x3)
    k_init<<<NCONV + NWC + NZERO, TB>>>(in_feat, wn[0], ws[0], wn[1], ws[1],
                                        wn[2], ws[2]);

    // idx1: cooperative fused CSR build
    {
        const int* a0 = src;
        const int* a1 = dst;
        void* args[] = { (void*)&a0, (void*)&a1 };
        cudaLaunchCooperativeKernel((void*)k_csr, dim3(148), dim3(1024), args, 0, 0);
    }

    // idx2: layer-1 GEMM
    k_gemm_pipe<<<gemmGrid, TB, GEMM_SMEM>>>(a, bh, bl, yn, ys);
    // idx3 (PROFILED): layer-1 aggregation
    k_agg<128, 1, 1><<<aggBlocks, TB>>>(yn, ys, bs[0], a, nullptr);
    // layer 2
    k_gemm_pipe<<<gemmGrid, TB, GEMM_SMEM>>>(a, bh + 32768, bl + 32768, yn, ys); // idx4
    k_agg<118, 1, 1><<<aggBlocks, TB>>>(yn, ys, bs[1], a, nullptr);              // idx5
    // layer 3
    k_gemm_pipe<<<gemmGrid, TB, GEMM_SMEM>>>(a, bh + 65536, bl + 65536, yn, ys); // idx6
    k_agg<103, 1, 0><<<aggBlocks, TB>>>(yn, ys, bs[2], nullptr, h3);             // idx7
    // layer 4 (SIMT, tiny) + pooling
    k_gemm4<<<(N_NODES + 15) / 16, TB>>>(h3, ws[3], wn[3], hs4, hn4);            // idx8
    k_agg4pool<<<(N_NODES + TB - 1) / TB, TB>>>(hn4, hs4, bs[3], gids);          // idx9
    k_final<<<1, 512>>>((float*)d_out);                                          // idx10
}